// round 14
// baseline (speedup 1.0000x reference)
#include <cuda_runtime.h>
#include <cuda_bf16.h>
#include <math.h>
#include <stdint.h>

// Problem dims
#define Bn 16384
#define Nn 64
#define Fn 128
#define Kn 64
#define NG 8          // clusters per CTA in main kernel
#define BT 256        // samples per CTA b-tile
#define THRV 2e-2f    // ambiguity threshold (relative) — ~28 sigma vs 7e-4 q-noise

// ---------------- device scratch (no allocations allowed) ----------------
__device__ __align__(16) __nv_bfloat16 gXhi[Bn * Fn];        // 4 MB
__device__ __align__(16) __nv_bfloat16 gWtHi[Nn * Kn * Fn];  // 1 MB  [n][k][i]
__device__ float gWf[Nn * Fn * Kn];                          // 2 MB  [n][i][k] fp32 (refine)
__device__ float gQ[Nn * Bn];                                // 4 MB
__device__ int   gFlagCnt;
__device__ int   gFlagIdx[Bn];
__device__ float gFlagQ[Bn];
__device__ unsigned long long gBest[Bn];                     // packed (q_bits<<32)|(63-n)

// ---------------- PTX helpers (portable sm_80+ subset) ----------------
__device__ __forceinline__ uint32_t smem_u32(const void* p) {
    uint32_t a;
    asm("{ .reg .u64 t; cvta.to.shared.u64 t, %1; cvt.u32.u64 %0, t; }" : "=r"(a) : "l"(p));
    return a;
}
__device__ __forceinline__ void ldm_x4(uint32_t& r0, uint32_t& r1, uint32_t& r2, uint32_t& r3,
                                       uint32_t addr) {
    asm volatile("ldmatrix.sync.aligned.m8n8.x4.shared.b16 {%0,%1,%2,%3}, [%4];"
                 : "=r"(r0), "=r"(r1), "=r"(r2), "=r"(r3) : "r"(addr));
}
__device__ __forceinline__ void mma_bf16(float* c, const uint32_t* a, const uint32_t* b) {
    asm volatile(
        "mma.sync.aligned.m16n8k16.row.col.f32.bf16.bf16.f32 "
        "{%0,%1,%2,%3}, {%4,%5,%6,%7}, {%8,%9}, {%0,%1,%2,%3};"
        : "+f"(c[0]), "+f"(c[1]), "+f"(c[2]), "+f"(c[3])
        : "r"(a[0]), "r"(a[1]), "r"(a[2]), "r"(a[3]), "r"(b[0]), "r"(b[1]));
}
#define CP_ASYNC16(dst, src) asm volatile("cp.async.cg.shared.global [%0], [%1], 16;" :: "r"(dst), "l"(src))
#define CP_COMMIT()          asm volatile("cp.async.commit_group;")
#define CP_WAIT0()           asm volatile("cp.async.wait_group 0;" ::: "memory")

// swizzled smem offset for a 16B chunk (row stride 256B = 128 bf16, 16 chunks/row)
__device__ __forceinline__ uint32_t swz(int r, int c) {
    return (uint32_t)(r * 256 + ((c ^ (r & 7)) << 4));
}

// ============================================================================
// Kernel 0: convert x to bf16; zero flag counter
// ============================================================================
__global__ void __launch_bounds__(256) convert_x_kernel(const float* __restrict__ x) {
    if (blockIdx.x == 0 && threadIdx.x == 0) gFlagCnt = 0;
    int base = (blockIdx.x * 256 + threadIdx.x) * 8;
    float4 a = *(const float4*)(x + base);
    float4 b = *(const float4*)(x + base + 4);
    float v[8] = {a.x, a.y, a.z, a.w, b.x, b.y, b.z, b.w};
    #pragma unroll
    for (int i = 0; i < 8; i++) gXhi[base + i] = __float2bfloat16_rn(v[i]);
}

// dummy: shifts ncu's capture index so next profile lands on main_kernel
__global__ void dummy_kernel() {}

// ============================================================================
// Kernel 1 (prep): per cluster n: A = D^T D ; div-free Cholesky ; solve
// W L^T = D per feature row ; emit Wt (bf16, [n][k][i]) and fp32 W ([n][i][k]).
// ============================================================================
__global__ void __launch_bounds__(256) prep_kernel(const float* __restrict__ D) {
    extern __shared__ float sm[];
    float* sD   = sm;                         // [128][64]
    float* sA   = sD + Fn * Kn;               // [64][65]
    float* sInv = sA + 64 * 65;               // [64]
    float* sW   = sInv + 64;                  // [128][65]

    const int n = blockIdx.x, tid = threadIdx.x;
    const float* Dn = D + n * Fn * Kn;

    for (int idx = tid; idx < Fn * Kn; idx += 256) sD[idx] = Dn[idx];
    __syncthreads();

    {   // DTD, 4x4 microtile per thread
        const int j0 = (tid >> 4) * 4, k0 = (tid & 15) * 4;
        float acc[4][4];
        #pragma unroll
        for (int a = 0; a < 4; a++)
            #pragma unroll
            for (int b = 0; b < 4; b++) acc[a][b] = 0.f;
        for (int i = 0; i < Fn; i++) {
            float av[4], bv[4];
            #pragma unroll
            for (int a = 0; a < 4; a++) av[a] = sD[i * 64 + j0 + a];
            #pragma unroll
            for (int b = 0; b < 4; b++) bv[b] = sD[i * 64 + k0 + b];
            #pragma unroll
            for (int a = 0; a < 4; a++)
                #pragma unroll
                for (int b = 0; b < 4; b++) acc[a][b] += av[a] * bv[b];
        }
        #pragma unroll
        for (int a = 0; a < 4; a++)
            #pragma unroll
            for (int b = 0; b < 4; b++) sA[(j0 + a) * 65 + (k0 + b)] = acc[a][b];
    }
    __syncthreads();

    // Cholesky, divide-free
    for (int k = 0; k < 64; k++) {
        if (tid == 0) {
            float a = sA[k * 65 + k];
            float r = rsqrtf(a);
            sA[k * 65 + k] = a * r;
            sInv[k] = r;
        }
        __syncthreads();
        if (tid > k && tid < 64) sA[tid * 65 + k] *= sInv[k];
        __syncthreads();
        for (int idx = tid; idx < 64 * 64; idx += 256) {
            int i = idx >> 6, j = idx & 63;
            if (i > k && j > k && j <= i)
                sA[i * 65 + j] -= sA[i * 65 + k] * sA[j * 65 + k];
        }
        __syncthreads();
    }

    // Solve w L^T = d per feature row i
    if (tid < Fn) {
        const int i = tid;
        float* w = sW + i * 65;
        for (int j = 0; j < 64; j++) {
            float s = sD[i * 64 + j];
            #pragma unroll 4
            for (int m = 0; m < j; m++) s -= sA[j * 65 + m] * w[m];
            w[j] = s * sInv[j];
        }
        for (int k = 0; k < 64; k++) {
            float v = w[k];
            gWtHi[(n * 64 + k) * Fn + i] = __float2bfloat16_rn(v);
            gWf[((size_t)n * Fn + i) * Kn + k] = v;   // fp32 for refine
        }
    }
}

// ============================================================================
// Kernel 2 (main): mma.sync bf16 single-pass GEMM + square-reduce.
// grid (64, 8) x 256 threads. CTA: 256 samples x 8 clusters. 96 KB smem -> 2 CTAs/SM.
// ============================================================================
#define SXH 0
#define SW0 65536
#define SM_TOTAL 98304

__global__ void __launch_bounds__(256, 2) main_kernel() {
    extern __shared__ char smem[];
    const uint32_t sb = smem_u32(smem);
    const int tid = threadIdx.x, wid = tid >> 5, lane = tid & 31;
    const int bt = blockIdx.x;

    {
        const char* srcH = (const char*)(gXhi + (size_t)bt * BT * Fn);
        #pragma unroll
        for (int t = 0; t < 16; t++) {
            int id = tid + t * 256;
            int r = id >> 4, c = id & 15;
            CP_ASYNC16(sb + SXH + swz(r, c), srcH + r * 256 + c * 16);
        }
    }
    {
        int n0 = blockIdx.y * NG;
        const char* srcH = (const char*)(gWtHi + (size_t)n0 * Kn * Fn);
        #pragma unroll
        for (int t = 0; t < 4; t++) {
            int id = tid + t * 256;
            int r = id >> 4, c = id & 15;
            CP_ASYNC16(sb + SW0 + swz(r, c), srcH + r * 256 + c * 16);
        }
    }
    CP_COMMIT();
    CP_WAIT0();
    __syncthreads();

    const int m0 = wid * 32;

    for (int j = 0; j < NG; j++) {
        const int n = blockIdx.y * NG + j;
        const uint32_t wb = sb + SW0 + (uint32_t)(j & 1) * 16384;

        if (j + 1 < NG) {
            const uint32_t pb = sb + SW0 + (uint32_t)((j + 1) & 1) * 16384;
            int nn = blockIdx.y * NG + j + 1;
            const char* srcH = (const char*)(gWtHi + (size_t)nn * Kn * Fn);
            #pragma unroll
            for (int t = 0; t < 4; t++) {
                int id = tid + t * 256;
                int r = id >> 4, c = id & 15;
                CP_ASYNC16(pb + swz(r, c), srcH + r * 256 + c * 16);
            }
            CP_COMMIT();
        }

        float acc[2][8][4];
        #pragma unroll
        for (int mt = 0; mt < 2; mt++)
            #pragma unroll
            for (int nt = 0; nt < 8; nt++)
                #pragma unroll
                for (int e = 0; e < 4; e++) acc[mt][nt][e] = 0.f;

        #pragma unroll
        for (int ks = 0; ks < 8; ks++) {
            const int c0 = 2 * ks;
            uint32_t Ah[2][4], Bh[8][2];
            #pragma unroll
            for (int mt = 0; mt < 2; mt++) {
                int row = m0 + mt * 16 + (lane & 15);
                int cc  = c0 + (lane >> 4);
                ldm_x4(Ah[mt][0], Ah[mt][1], Ah[mt][2], Ah[mt][3], sb + SXH + swz(row, cc));
            }
            #pragma unroll
            for (int np = 0; np < 4; np++) {
                int nrow = np * 16 + (lane & 7) + ((lane >> 4) << 3);
                int cc   = c0 + ((lane >> 3) & 1);
                ldm_x4(Bh[np*2][0], Bh[np*2][1], Bh[np*2+1][0], Bh[np*2+1][1], wb + swz(nrow, cc));
            }
            #pragma unroll
            for (int mt = 0; mt < 2; mt++)
                #pragma unroll
                for (int nt = 0; nt < 8; nt++)
                    mma_bf16(acc[mt][nt], Ah[mt], Bh[nt]);
        }

        float pa = 0.f, pb2 = 0.f, pc = 0.f, pd = 0.f;
        #pragma unroll
        for (int nt = 0; nt < 8; nt++) {
            pa  += acc[0][nt][0] * acc[0][nt][0] + acc[0][nt][1] * acc[0][nt][1];
            pb2 += acc[0][nt][2] * acc[0][nt][2] + acc[0][nt][3] * acc[0][nt][3];
            pc  += acc[1][nt][0] * acc[1][nt][0] + acc[1][nt][1] * acc[1][nt][1];
            pd  += acc[1][nt][2] * acc[1][nt][2] + acc[1][nt][3] * acc[1][nt][3];
        }
        #pragma unroll
        for (int o = 1; o <= 2; o <<= 1) {
            pa  += __shfl_xor_sync(0xFFFFFFFFu, pa, o);
            pb2 += __shfl_xor_sync(0xFFFFFFFFu, pb2, o);
            pc  += __shfl_xor_sync(0xFFFFFFFFu, pc, o);
            pd  += __shfl_xor_sync(0xFFFFFFFFu, pd, o);
        }
        if ((lane & 3) == 0) {
            int r = lane >> 2;
            float* q = gQ + (size_t)n * Bn + bt * BT + m0;
            q[r]      = pa;
            q[r + 8]  = pb2;
            q[r + 16] = pc;
            q[r + 24] = pd;
        }

        CP_WAIT0();
        __syncthreads();
    }
}

// ============================================================================
// Kernel 3: argmax over n (4 lanes/sample); flag ambiguous (init gBest);
// labels + warp-reduced loss.
// ============================================================================
__global__ void __launch_bounds__(256) reduce_kernel(const float* __restrict__ x,
                                                     float* __restrict__ out,
                                                     int out_size) {
    const int g = threadIdx.x & 3;
    const int b = (blockIdx.x * 256 + threadIdx.x) >> 2;
    const int lane = threadIdx.x & 31;

    float q1 = -1e30f, q2 = -1e30f;
    int i1 = 0;
    #pragma unroll
    for (int t = 0; t < 16; t++) {
        int n = t * 4 + g;
        float v = gQ[n * Bn + b];
        if (v > q1)      { q2 = q1; q1 = v; i1 = n; }
        else if (v > q2) { q2 = v; }
    }
    #pragma unroll
    for (int o = 1; o <= 2; o <<= 1) {
        float oq1 = __shfl_xor_sync(0xFFFFFFFFu, q1, o);
        int   oi1 = __shfl_xor_sync(0xFFFFFFFFu, i1, o);
        float oq2 = __shfl_xor_sync(0xFFFFFFFFu, q2, o);
        if (oq1 > q1 || (oq1 == q1 && oi1 < i1)) {
            q2 = fmaxf(q1, fmaxf(q2, oq2));
            q1 = oq1; i1 = oi1;
        } else {
            q2 = fmaxf(oq1, fmaxf(q2, oq2));
        }
    }

    float xn2 = 0.f;
    const float4* xb = (const float4*)(x + (size_t)b * Fn);
    #pragma unroll
    for (int t = 0; t < 8; t++) {
        float4 f = xb[g + t * 4];
        xn2 += f.x * f.x + f.y * f.y + f.z * f.z + f.w * f.w;
    }
    #pragma unroll
    for (int o = 1; o <= 2; o <<= 1) xn2 += __shfl_xor_sync(0xFFFFFFFFu, xn2, o);

    if (g == 0) {
        if (out_size >= Bn + 1)  out[1 + b] = (float)i1;
        else if (out_size == Bn) out[b] = (float)i1;
        if (q1 - q2 < q1 * THRV) {
            int slot = atomicAdd(&gFlagCnt, 1);
            gFlagIdx[slot] = b;
            gFlagQ[slot] = q1;
            gBest[b] = 0ull;              // reset for refine's atomicMax
        }
    }

    float resid = 0.25f * (xn2 - q1);
    #pragma unroll
    for (int o = 16; o; o >>= 1) resid += __shfl_xor_sync(0xFFFFFFFFu, resid, o);
    if (lane == 0 && out_size != Bn) atomicAdd(&out[0], resid);
}

// ============================================================================
// Kernel 4: cluster-major exact refine. One CTA per cluster; W[n] fp32 in smem.
// For each flagged sample whose approx q_n is within threshold of its max,
// compute exact q and atomicMax packed (q, 63-n) into gBest[b].
// ============================================================================
__global__ void __launch_bounds__(256) refineA_kernel(const float* __restrict__ x) {
    __shared__ float sW[Fn * Kn];      // 32 KB, [i][k]
    __shared__ float sx[8][Fn];        // per-warp x cache
    const int n = blockIdx.x;
    const int wid = threadIdx.x >> 5, lane = threadIdx.x & 31;

    const float4* src = (const float4*)(gWf + (size_t)n * Fn * Kn);
    for (int i = threadIdx.x; i < Fn * Kn / 4; i += 256) ((float4*)sW)[i] = src[i];
    __syncthreads();

    const int cnt = gFlagCnt;
    for (int fi = wid; fi < cnt; fi += 8) {
        const int b = gFlagIdx[fi];
        const float qA = gFlagQ[fi];
        const float qn = gQ[n * Bn + b];
        if (qn < qA * (1.0f - THRV)) continue;

        #pragma unroll
        for (int t = 0; t < 4; t++) sx[wid][lane + t * 32] = x[(size_t)b * Fn + lane + t * 32];
        __syncwarp();

        const float2* Wp = (const float2*)(sW + 2 * lane);   // lane owns k=2l,2l+1
        float z0 = 0.f, z1 = 0.f;
        #pragma unroll 8
        for (int i = 0; i < Fn; i++) {
            float xi = sx[wid][i];
            float2 wv = Wp[i * 32];
            z0 += xi * wv.x;
            z1 += xi * wv.y;
        }
        float qp = z0 * z0 + z1 * z1;
        #pragma unroll
        for (int o = 16; o; o >>= 1) qp += __shfl_xor_sync(0xFFFFFFFFu, qp, o);
        if (lane == 0) {
            unsigned long long pk = (((unsigned long long)__float_as_uint(qp)) << 32)
                                  | (unsigned)(Nn - 1 - n);   // smaller n wins ties
            atomicMax(&gBest[b], pk);
        }
        __syncwarp();
    }
}

// ============================================================================
// Kernel 5: fixup — write exact labels and loss corrections for flagged samples.
// ============================================================================
__global__ void __launch_bounds__(256) fixup_kernel(float* __restrict__ out, int out_size) {
    const int t = blockIdx.x * 256 + threadIdx.x;
    if (t >= gFlagCnt) return;
    const int b = gFlagIdx[t];
    const float qA = gFlagQ[t];
    unsigned long long pk = gBest[b];
    float qE = __uint_as_float((unsigned)(pk >> 32));
    int   nE = Nn - 1 - (int)(pk & 0xFFFFFFFFull);
    if (out_size >= Bn + 1)  out[1 + b] = (float)nE;
    else if (out_size == Bn) out[b] = (float)nE;
    if (out_size != Bn) atomicAdd(&out[0], qA - qE);   // replace approx term with exact
}

// ============================================================================
extern "C" void kernel_launch(void* const* d_in, const int* in_sizes, int n_in,
                              void* d_out, int out_size) {
    const float* x;
    const float* D;
    if (in_sizes[0] == Bn * Fn) { x = (const float*)d_in[0]; D = (const float*)d_in[1]; }
    else                        { x = (const float*)d_in[1]; D = (const float*)d_in[0]; }
    float* out = (float*)d_out;

    const int SMEM_PREP = (Fn * Kn + 64 * 65 + 64 + Fn * 65) * 4;
    cudaFuncSetAttribute(prep_kernel, cudaFuncAttributeMaxDynamicSharedMemorySize, SMEM_PREP);
    cudaFuncSetAttribute(main_kernel, cudaFuncAttributeMaxDynamicSharedMemorySize, SM_TOTAL);

    convert_x_kernel<<<Bn * Fn / (256 * 8), 256>>>(x);
    prep_kernel<<<Nn, 256, SMEM_PREP>>>(D);
    dummy_kernel<<<1, 32>>>();                      // shifts ncu capture index toward main
    main_kernel<<<dim3(Bn / BT, Nn / NG), 256, SM_TOTAL>>>();
    if (out_size != Bn) cudaMemsetAsync(d_out, 0, sizeof(float));
    reduce_kernel<<<Bn * 4 / 256, 256>>>(x, out, out_size);
    refineA_kernel<<<Nn, 256>>>(x);
    fixup_kernel<<<Bn / 256, 256>>>(out, out_size);
}

// round 15
// speedup vs baseline: 1.9230x; 1.9230x over previous
#include <cuda_runtime.h>
#include <cuda_bf16.h>
#include <math.h>
#include <stdint.h>

// Problem dims
#define Bn 16384
#define Nn 64
#define Fn 128
#define Kn 64
#define NG 8          // clusters per CTA in main kernel
#define BT 256        // samples per CTA b-tile
#define THRV 8e-3f    // ambiguity threshold (~8 sigma vs ~1e-3 pair-diff noise)
#define MAXPAIR (Bn * 8)

// ---------------- device scratch (no allocations allowed) ----------------
__device__ __align__(16) __nv_bfloat16 gXhi[Bn * Fn];        // 4 MB
__device__ __align__(16) __nv_bfloat16 gWtHi[Nn * Kn * Fn];  // 1 MB  [n][k][i]
__device__ float gWf[Nn * Fn * Kn];                          // 2 MB  [n][i][k] fp32 (refine)
__device__ float gQ[Nn * Bn];                                // 4 MB
__device__ int   gFlagCnt;
__device__ int   gPairCnt;
__device__ int   gFlagIdx[Bn];
__device__ float gFlagQ[Bn];
__device__ int   gPair[MAXPAIR];                             // (b<<6)|n
__device__ unsigned long long gBest[Bn];                     // packed (q_bits<<32)|(63-n)

// ---------------- PTX helpers (portable sm_80+ subset) ----------------
__device__ __forceinline__ uint32_t smem_u32(const void* p) {
    uint32_t a;
    asm("{ .reg .u64 t; cvta.to.shared.u64 t, %1; cvt.u32.u64 %0, t; }" : "=r"(a) : "l"(p));
    return a;
}
__device__ __forceinline__ void ldm_x4(uint32_t& r0, uint32_t& r1, uint32_t& r2, uint32_t& r3,
                                       uint32_t addr) {
    asm volatile("ldmatrix.sync.aligned.m8n8.x4.shared.b16 {%0,%1,%2,%3}, [%4];"
                 : "=r"(r0), "=r"(r1), "=r"(r2), "=r"(r3) : "r"(addr));
}
__device__ __forceinline__ void mma_bf16(float* c, const uint32_t* a, const uint32_t* b) {
    asm volatile(
        "mma.sync.aligned.m16n8k16.row.col.f32.bf16.bf16.f32 "
        "{%0,%1,%2,%3}, {%4,%5,%6,%7}, {%8,%9}, {%0,%1,%2,%3};"
        : "+f"(c[0]), "+f"(c[1]), "+f"(c[2]), "+f"(c[3])
        : "r"(a[0]), "r"(a[1]), "r"(a[2]), "r"(a[3]), "r"(b[0]), "r"(b[1]));
}
#define CP_ASYNC16(dst, src) asm volatile("cp.async.cg.shared.global [%0], [%1], 16;" :: "r"(dst), "l"(src))
#define CP_COMMIT()          asm volatile("cp.async.commit_group;")
#define CP_WAIT0()           asm volatile("cp.async.wait_group 0;" ::: "memory")

__device__ __forceinline__ uint32_t swz(int r, int c) {
    return (uint32_t)(r * 256 + ((c ^ (r & 7)) << 4));
}

// ============================================================================
// Kernel 0: convert x to bf16; zero counters
// ============================================================================
__global__ void __launch_bounds__(256) convert_x_kernel(const float* __restrict__ x) {
    if (blockIdx.x == 0 && threadIdx.x == 0) { gFlagCnt = 0; gPairCnt = 0; }
    int base = (blockIdx.x * 256 + threadIdx.x) * 8;
    float4 a = *(const float4*)(x + base);
    float4 b = *(const float4*)(x + base + 4);
    float v[8] = {a.x, a.y, a.z, a.w, b.x, b.y, b.z, b.w};
    #pragma unroll
    for (int i = 0; i < 8; i++) gXhi[base + i] = __float2bfloat16_rn(v[i]);
}

__global__ void dummy_kernel() {}

// ============================================================================
// Kernel 1 (prep): per cluster n: A = D^T D ; div-free Cholesky ; solve
// W L^T = D per feature row ; emit Wt (bf16, [n][k][i]) and fp32 W ([n][i][k]).
// ============================================================================
__global__ void __launch_bounds__(256) prep_kernel(const float* __restrict__ D) {
    extern __shared__ float sm[];
    float* sD   = sm;                         // [128][64]
    float* sA   = sD + Fn * Kn;               // [64][65]
    float* sInv = sA + 64 * 65;               // [64]
    float* sW   = sInv + 64;                  // [128][65]

    const int n = blockIdx.x, tid = threadIdx.x;
    const float* Dn = D + n * Fn * Kn;

    for (int idx = tid; idx < Fn * Kn; idx += 256) sD[idx] = Dn[idx];
    __syncthreads();

    {   // DTD, 4x4 microtile per thread
        const int j0 = (tid >> 4) * 4, k0 = (tid & 15) * 4;
        float acc[4][4];
        #pragma unroll
        for (int a = 0; a < 4; a++)
            #pragma unroll
            for (int b = 0; b < 4; b++) acc[a][b] = 0.f;
        for (int i = 0; i < Fn; i++) {
            float av[4], bv[4];
            #pragma unroll
            for (int a = 0; a < 4; a++) av[a] = sD[i * 64 + j0 + a];
            #pragma unroll
            for (int b = 0; b < 4; b++) bv[b] = sD[i * 64 + k0 + b];
            #pragma unroll
            for (int a = 0; a < 4; a++)
                #pragma unroll
                for (int b = 0; b < 4; b++) acc[a][b] += av[a] * bv[b];
        }
        #pragma unroll
        for (int a = 0; a < 4; a++)
            #pragma unroll
            for (int b = 0; b < 4; b++) sA[(j0 + a) * 65 + (k0 + b)] = acc[a][b];
    }
    __syncthreads();

    for (int k = 0; k < 64; k++) {
        if (tid == 0) {
            float a = sA[k * 65 + k];
            float r = rsqrtf(a);
            sA[k * 65 + k] = a * r;
            sInv[k] = r;
        }
        __syncthreads();
        if (tid > k && tid < 64) sA[tid * 65 + k] *= sInv[k];
        __syncthreads();
        for (int idx = tid; idx < 64 * 64; idx += 256) {
            int i = idx >> 6, j = idx & 63;
            if (i > k && j > k && j <= i)
                sA[i * 65 + j] -= sA[i * 65 + k] * sA[j * 65 + k];
        }
        __syncthreads();
    }

    if (tid < Fn) {
        const int i = tid;
        float* w = sW + i * 65;
        for (int j = 0; j < 64; j++) {
            float s = sD[i * 64 + j];
            #pragma unroll 4
            for (int m = 0; m < j; m++) s -= sA[j * 65 + m] * w[m];
            w[j] = s * sInv[j];
        }
        for (int k = 0; k < 64; k++) {
            float v = w[k];
            gWtHi[(n * 64 + k) * Fn + i] = __float2bfloat16_rn(v);
            gWf[((size_t)n * Fn + i) * Kn + k] = v;
        }
    }
}

// ============================================================================
// Kernel 2 (main): mma.sync bf16 single-pass GEMM + square-reduce. (unchanged)
// ============================================================================
#define SXH 0
#define SW0 65536
#define SM_TOTAL 98304

__global__ void __launch_bounds__(256, 2) main_kernel() {
    extern __shared__ char smem[];
    const uint32_t sb = smem_u32(smem);
    const int tid = threadIdx.x, wid = tid >> 5, lane = tid & 31;
    const int bt = blockIdx.x;

    {
        const char* srcH = (const char*)(gXhi + (size_t)bt * BT * Fn);
        #pragma unroll
        for (int t = 0; t < 16; t++) {
            int id = tid + t * 256;
            int r = id >> 4, c = id & 15;
            CP_ASYNC16(sb + SXH + swz(r, c), srcH + r * 256 + c * 16);
        }
    }
    {
        int n0 = blockIdx.y * NG;
        const char* srcH = (const char*)(gWtHi + (size_t)n0 * Kn * Fn);
        #pragma unroll
        for (int t = 0; t < 4; t++) {
            int id = tid + t * 256;
            int r = id >> 4, c = id & 15;
            CP_ASYNC16(sb + SW0 + swz(r, c), srcH + r * 256 + c * 16);
        }
    }
    CP_COMMIT();
    CP_WAIT0();
    __syncthreads();

    const int m0 = wid * 32;

    for (int j = 0; j < NG; j++) {
        const int n = blockIdx.y * NG + j;
        const uint32_t wb = sb + SW0 + (uint32_t)(j & 1) * 16384;

        if (j + 1 < NG) {
            const uint32_t pb = sb + SW0 + (uint32_t)((j + 1) & 1) * 16384;
            int nn = blockIdx.y * NG + j + 1;
            const char* srcH = (const char*)(gWtHi + (size_t)nn * Kn * Fn);
            #pragma unroll
            for (int t = 0; t < 4; t++) {
                int id = tid + t * 256;
                int r = id >> 4, c = id & 15;
                CP_ASYNC16(pb + swz(r, c), srcH + r * 256 + c * 16);
            }
            CP_COMMIT();
        }

        float acc[2][8][4];
        #pragma unroll
        for (int mt = 0; mt < 2; mt++)
            #pragma unroll
            for (int nt = 0; nt < 8; nt++)
                #pragma unroll
                for (int e = 0; e < 4; e++) acc[mt][nt][e] = 0.f;

        #pragma unroll
        for (int ks = 0; ks < 8; ks++) {
            const int c0 = 2 * ks;
            uint32_t Ah[2][4], Bh[8][2];
            #pragma unroll
            for (int mt = 0; mt < 2; mt++) {
                int row = m0 + mt * 16 + (lane & 15);
                int cc  = c0 + (lane >> 4);
                ldm_x4(Ah[mt][0], Ah[mt][1], Ah[mt][2], Ah[mt][3], sb + SXH + swz(row, cc));
            }
            #pragma unroll
            for (int np = 0; np < 4; np++) {
                int nrow = np * 16 + (lane & 7) + ((lane >> 4) << 3);
                int cc   = c0 + ((lane >> 3) & 1);
                ldm_x4(Bh[np*2][0], Bh[np*2][1], Bh[np*2+1][0], Bh[np*2+1][1], wb + swz(nrow, cc));
            }
            #pragma unroll
            for (int mt = 0; mt < 2; mt++)
                #pragma unroll
                for (int nt = 0; nt < 8; nt++)
                    mma_bf16(acc[mt][nt], Ah[mt], Bh[nt]);
        }

        float pa = 0.f, pb2 = 0.f, pc = 0.f, pd = 0.f;
        #pragma unroll
        for (int nt = 0; nt < 8; nt++) {
            pa  += acc[0][nt][0] * acc[0][nt][0] + acc[0][nt][1] * acc[0][nt][1];
            pb2 += acc[0][nt][2] * acc[0][nt][2] + acc[0][nt][3] * acc[0][nt][3];
            pc  += acc[1][nt][0] * acc[1][nt][0] + acc[1][nt][1] * acc[1][nt][1];
            pd  += acc[1][nt][2] * acc[1][nt][2] + acc[1][nt][3] * acc[1][nt][3];
        }
        #pragma unroll
        for (int o = 1; o <= 2; o <<= 1) {
            pa  += __shfl_xor_sync(0xFFFFFFFFu, pa, o);
            pb2 += __shfl_xor_sync(0xFFFFFFFFu, pb2, o);
            pc  += __shfl_xor_sync(0xFFFFFFFFu, pc, o);
            pd  += __shfl_xor_sync(0xFFFFFFFFu, pd, o);
        }
        if ((lane & 3) == 0) {
            int r = lane >> 2;
            float* q = gQ + (size_t)n * Bn + bt * BT + m0;
            q[r]      = pa;
            q[r + 8]  = pb2;
            q[r + 16] = pc;
            q[r + 24] = pd;
        }

        CP_WAIT0();
        __syncthreads();
    }
}

// ============================================================================
// Kernel 3: argmax over n (4 lanes/sample, q's kept in registers);
// flag ambiguous + emit candidate pairs HERE (no later gQ re-scan);
// labels + warp-reduced loss.
// ============================================================================
__global__ void __launch_bounds__(256) reduce_kernel(const float* __restrict__ x,
                                                     float* __restrict__ out,
                                                     int out_size) {
    const int g = threadIdx.x & 3;
    const int b = (blockIdx.x * 256 + threadIdx.x) >> 2;
    const int lane = threadIdx.x & 31;

    float v[16];
    float q1 = -1e30f, q2 = -1e30f;
    int i1 = 0;
    #pragma unroll
    for (int t = 0; t < 16; t++) {
        int n = t * 4 + g;
        v[t] = gQ[n * Bn + b];
        if (v[t] > q1)      { q2 = q1; q1 = v[t]; i1 = n; }
        else if (v[t] > q2) { q2 = v[t]; }
    }
    #pragma unroll
    for (int o = 1; o <= 2; o <<= 1) {
        float oq1 = __shfl_xor_sync(0xFFFFFFFFu, q1, o);
        int   oi1 = __shfl_xor_sync(0xFFFFFFFFu, i1, o);
        float oq2 = __shfl_xor_sync(0xFFFFFFFFu, q2, o);
        if (oq1 > q1 || (oq1 == q1 && oi1 < i1)) {
            q2 = fmaxf(q1, fmaxf(q2, oq2));
            q1 = oq1; i1 = oi1;
        } else {
            q2 = fmaxf(oq1, fmaxf(q2, oq2));
        }
    }

    float xn2 = 0.f;
    const float4* xb = (const float4*)(x + (size_t)b * Fn);
    #pragma unroll
    for (int t = 0; t < 8; t++) {
        float4 f = xb[g + t * 4];
        xn2 += f.x * f.x + f.y * f.y + f.z * f.z + f.w * f.w;
    }
    #pragma unroll
    for (int o = 1; o <= 2; o <<= 1) xn2 += __shfl_xor_sync(0xFFFFFFFFu, xn2, o);

    const bool flagged = (q1 - q2 < q1 * THRV);

    if (g == 0) {
        if (out_size >= Bn + 1)  out[1 + b] = (float)i1;
        else if (out_size == Bn) out[b] = (float)i1;
        if (flagged) {
            int slot = atomicAdd(&gFlagCnt, 1);
            gFlagIdx[slot] = b;
            gFlagQ[slot] = q1;
            gBest[b] = 0ull;
        }
    }
    // every lane emits its qualifying candidates (argmax included by construction)
    if (flagged) {
        const float cut = q1 * (1.0f - THRV);
        #pragma unroll
        for (int t = 0; t < 16; t++) {
            if (v[t] >= cut) {
                int pos = atomicAdd(&gPairCnt, 1);
                if (pos < MAXPAIR) gPair[pos] = (b << 6) | (t * 4 + g);
            }
        }
    }

    float resid = 0.25f * (xn2 - q1);
    #pragma unroll
    for (int o = 16; o; o >>= 1) resid += __shfl_xor_sync(0xFFFFFFFFu, resid, o);
    if (lane == 0 && out_size != Bn) atomicAdd(&out[0], resid);
}

// ============================================================================
// Kernel 4: pair-parallel exact refine. One warp per (b,n) pair, grid-stride.
// No gQ scanning; W streamed from L2 with MLP; atomicMax into gBest.
// ============================================================================
__global__ void __launch_bounds__(128) refine_kernel(const float* __restrict__ x) {
    __shared__ float sx[4][Fn];
    const int wid = threadIdx.x >> 5, lane = threadIdx.x & 31;
    const int cnt = min(gPairCnt, MAXPAIR);

    for (int pi = blockIdx.x * 4 + wid; pi < cnt; pi += gridDim.x * 4) {
        const int p = gPair[pi];
        const int b = p >> 6, n = p & 63;

        ((float4*)sx[wid])[lane] = ((const float4*)(x + (size_t)b * Fn))[lane];
        __syncwarp();

        const float2* Wp = (const float2*)(gWf + (size_t)n * Fn * Kn + 2 * lane);
        float z0 = 0.f, z1 = 0.f;
        #pragma unroll 8
        for (int i = 0; i < Fn; i++) {
            float xi = sx[wid][i];
            float2 wv = Wp[(size_t)i * 32];
            z0 += xi * wv.x;
            z1 += xi * wv.y;
        }
        float qp = z0 * z0 + z1 * z1;
        #pragma unroll
        for (int o = 16; o; o >>= 1) qp += __shfl_xor_sync(0xFFFFFFFFu, qp, o);
        if (lane == 0) {
            unsigned long long pk = (((unsigned long long)__float_as_uint(qp)) << 32)
                                  | (unsigned)(Nn - 1 - n);   // smaller n wins ties
            atomicMax(&gBest[b], pk);
        }
        __syncwarp();
    }
}

// ============================================================================
// Kernel 5: fixup — exact labels + loss corrections for flagged samples.
// ============================================================================
__global__ void __launch_bounds__(256) fixup_kernel(float* __restrict__ out, int out_size) {
    const int t = blockIdx.x * 256 + threadIdx.x;
    if (t >= gFlagCnt) return;
    const int b = gFlagIdx[t];
    const float qA = gFlagQ[t];
    unsigned long long pk = gBest[b];
    float qE = __uint_as_float((unsigned)(pk >> 32));
    int   nE = Nn - 1 - (int)(pk & 0xFFFFFFFFull);
    if (out_size >= Bn + 1)  out[1 + b] = (float)nE;
    else if (out_size == Bn) out[b] = (float)nE;
    if (out_size != Bn) atomicAdd(&out[0], qA - qE);
}

// ============================================================================
extern "C" void kernel_launch(void* const* d_in, const int* in_sizes, int n_in,
                              void* d_out, int out_size) {
    const float* x;
    const float* D;
    if (in_sizes[0] == Bn * Fn) { x = (const float*)d_in[0]; D = (const float*)d_in[1]; }
    else                        { x = (const float*)d_in[1]; D = (const float*)d_in[0]; }
    float* out = (float*)d_out;

    const int SMEM_PREP = (Fn * Kn + 64 * 65 + 64 + Fn * 65) * 4;
    cudaFuncSetAttribute(prep_kernel, cudaFuncAttributeMaxDynamicSharedMemorySize, SMEM_PREP);
    cudaFuncSetAttribute(main_kernel, cudaFuncAttributeMaxDynamicSharedMemorySize, SM_TOTAL);

    convert_x_kernel<<<Bn * Fn / (256 * 8), 256>>>(x);
    prep_kernel<<<Nn, 256, SMEM_PREP>>>(D);
    dummy_kernel<<<1, 32>>>();
    main_kernel<<<dim3(Bn / BT, Nn / NG), 256, SM_TOTAL>>>();
    if (out_size != Bn) cudaMemsetAsync(d_out, 0, sizeof(float));
    reduce_kernel<<<Bn * 4 / 256, 256>>>(x, out, out_size);
    refine_kernel<<<256, 128>>>(x);
    fixup_kernel<<<Bn / 256, 256>>>(out, out_size);
}

// round 16
// speedup vs baseline: 2.2552x; 1.1728x over previous
#include <cuda_runtime.h>
#include <cuda_bf16.h>
#include <math.h>
#include <stdint.h>

// Problem dims
#define Bn 16384
#define Nn 64
#define Fn 128
#define Kn 64
#define NG 8          // clusters per CTA in main kernel
#define BT 256        // samples per CTA b-tile
#define THRV 5e-3f    // ambiguity threshold (~7 sigma vs ~7e-4 pair-diff noise)
#define MAXPAIR (Bn * 32)

// ---------------- device scratch (no allocations allowed) ----------------
__device__ __align__(16) __nv_bfloat16 gXhi[Bn * Fn];        // 4 MB
__device__ __align__(16) __nv_bfloat16 gWtHi[Nn * Kn * Fn];  // 1 MB  [n][k][i]
__device__ float gWf[Nn * Fn * Kn];                          // 2 MB  [n][i][k] fp32 (refine)
__device__ float gQ[Nn * Bn];                                // 4 MB
__device__ int   gFlagCnt;
__device__ int   gPairCnt;
__device__ int   gFlagIdx[Bn];
__device__ float gFlagQ[Bn];
__device__ int   gPair[MAXPAIR];                             // (b<<6)|n
__device__ unsigned long long gBest[Bn];                     // packed (q_bits<<32)|(63-n)

// ---------------- PTX helpers (portable sm_80+ subset) ----------------
__device__ __forceinline__ uint32_t smem_u32(const void* p) {
    uint32_t a;
    asm("{ .reg .u64 t; cvta.to.shared.u64 t, %1; cvt.u32.u64 %0, t; }" : "=r"(a) : "l"(p));
    return a;
}
__device__ __forceinline__ void ldm_x4(uint32_t& r0, uint32_t& r1, uint32_t& r2, uint32_t& r3,
                                       uint32_t addr) {
    asm volatile("ldmatrix.sync.aligned.m8n8.x4.shared.b16 {%0,%1,%2,%3}, [%4];"
                 : "=r"(r0), "=r"(r1), "=r"(r2), "=r"(r3) : "r"(addr));
}
__device__ __forceinline__ void mma_bf16(float* c, const uint32_t* a, const uint32_t* b) {
    asm volatile(
        "mma.sync.aligned.m16n8k16.row.col.f32.bf16.bf16.f32 "
        "{%0,%1,%2,%3}, {%4,%5,%6,%7}, {%8,%9}, {%0,%1,%2,%3};"
        : "+f"(c[0]), "+f"(c[1]), "+f"(c[2]), "+f"(c[3])
        : "r"(a[0]), "r"(a[1]), "r"(a[2]), "r"(a[3]), "r"(b[0]), "r"(b[1]));
}
#define CP_ASYNC16(dst, src) asm volatile("cp.async.cg.shared.global [%0], [%1], 16;" :: "r"(dst), "l"(src))
#define CP_COMMIT()          asm volatile("cp.async.commit_group;")
#define CP_WAIT0()           asm volatile("cp.async.wait_group 0;" ::: "memory")

__device__ __forceinline__ uint32_t swz(int r, int c) {
    return (uint32_t)(r * 256 + ((c ^ (r & 7)) << 4));
}

// ============================================================================
// Kernel 0: convert x to bf16; zero counters
// ============================================================================
__global__ void __launch_bounds__(256) convert_x_kernel(const float* __restrict__ x) {
    if (blockIdx.x == 0 && threadIdx.x == 0) { gFlagCnt = 0; gPairCnt = 0; }
    int base = (blockIdx.x * 256 + threadIdx.x) * 8;
    float4 a = *(const float4*)(x + base);
    float4 b = *(const float4*)(x + base + 4);
    float v[8] = {a.x, a.y, a.z, a.w, b.x, b.y, b.z, b.w};
    #pragma unroll
    for (int i = 0; i < 8; i++) gXhi[base + i] = __float2bfloat16_rn(v[i]);
}

__global__ void dummy_kernel() {}

// ============================================================================
// Kernel 1 (prep): per cluster n: A = D^T D ; div-free Cholesky ; solve
// W L^T = D per feature row ; emit Wt (bf16, [n][k][i]) and fp32 W ([n][i][k]).
// ============================================================================
__global__ void __launch_bounds__(256) prep_kernel(const float* __restrict__ D) {
    extern __shared__ float sm[];
    float* sD   = sm;                         // [128][64]
    float* sA   = sD + Fn * Kn;               // [64][65]
    float* sInv = sA + 64 * 65;               // [64]
    float* sW   = sInv + 64;                  // [128][65]

    const int n = blockIdx.x, tid = threadIdx.x;
    const float* Dn = D + n * Fn * Kn;

    for (int idx = tid; idx < Fn * Kn; idx += 256) sD[idx] = Dn[idx];
    __syncthreads();

    {   // DTD, 4x4 microtile per thread
        const int j0 = (tid >> 4) * 4, k0 = (tid & 15) * 4;
        float acc[4][4];
        #pragma unroll
        for (int a = 0; a < 4; a++)
            #pragma unroll
            for (int b = 0; b < 4; b++) acc[a][b] = 0.f;
        for (int i = 0; i < Fn; i++) {
            float av[4], bv[4];
            #pragma unroll
            for (int a = 0; a < 4; a++) av[a] = sD[i * 64 + j0 + a];
            #pragma unroll
            for (int b = 0; b < 4; b++) bv[b] = sD[i * 64 + k0 + b];
            #pragma unroll
            for (int a = 0; a < 4; a++)
                #pragma unroll
                for (int b = 0; b < 4; b++) acc[a][b] += av[a] * bv[b];
        }
        #pragma unroll
        for (int a = 0; a < 4; a++)
            #pragma unroll
            for (int b = 0; b < 4; b++) sA[(j0 + a) * 65 + (k0 + b)] = acc[a][b];
    }
    __syncthreads();

    for (int k = 0; k < 64; k++) {
        if (tid == 0) {
            float a = sA[k * 65 + k];
            float r = rsqrtf(a);
            sA[k * 65 + k] = a * r;
            sInv[k] = r;
        }
        __syncthreads();
        if (tid > k && tid < 64) sA[tid * 65 + k] *= sInv[k];
        __syncthreads();
        for (int idx = tid; idx < 64 * 64; idx += 256) {
            int i = idx >> 6, j = idx & 63;
            if (i > k && j > k && j <= i)
                sA[i * 65 + j] -= sA[i * 65 + k] * sA[j * 65 + k];
        }
        __syncthreads();
    }

    if (tid < Fn) {
        const int i = tid;
        float* w = sW + i * 65;
        for (int j = 0; j < 64; j++) {
            float s = sD[i * 64 + j];
            #pragma unroll 4
            for (int m = 0; m < j; m++) s -= sA[j * 65 + m] * w[m];
            w[j] = s * sInv[j];
        }
        for (int k = 0; k < 64; k++) {
            float v = w[k];
            gWtHi[(n * 64 + k) * Fn + i] = __float2bfloat16_rn(v);
            gWf[((size_t)n * Fn + i) * Kn + k] = v;
        }
    }
}

// ============================================================================
// Kernel 2 (main): mma.sync bf16 single-pass GEMM + square-reduce. (unchanged)
// ============================================================================
#define SXH 0
#define SW0 65536
#define SM_TOTAL 98304

__global__ void __launch_bounds__(256, 2) main_kernel() {
    extern __shared__ char smem[];
    const uint32_t sb = smem_u32(smem);
    const int tid = threadIdx.x, wid = tid >> 5, lane = tid & 31;
    const int bt = blockIdx.x;

    {
        const char* srcH = (const char*)(gXhi + (size_t)bt * BT * Fn);
        #pragma unroll
        for (int t = 0; t < 16; t++) {
            int id = tid + t * 256;
            int r = id >> 4, c = id & 15;
            CP_ASYNC16(sb + SXH + swz(r, c), srcH + r * 256 + c * 16);
        }
    }
    {
        int n0 = blockIdx.y * NG;
        const char* srcH = (const char*)(gWtHi + (size_t)n0 * Kn * Fn);
        #pragma unroll
        for (int t = 0; t < 4; t++) {
            int id = tid + t * 256;
            int r = id >> 4, c = id & 15;
            CP_ASYNC16(sb + SW0 + swz(r, c), srcH + r * 256 + c * 16);
        }
    }
    CP_COMMIT();
    CP_WAIT0();
    __syncthreads();

    const int m0 = wid * 32;

    for (int j = 0; j < NG; j++) {
        const int n = blockIdx.y * NG + j;
        const uint32_t wb = sb + SW0 + (uint32_t)(j & 1) * 16384;

        if (j + 1 < NG) {
            const uint32_t pb = sb + SW0 + (uint32_t)((j + 1) & 1) * 16384;
            int nn = blockIdx.y * NG + j + 1;
            const char* srcH = (const char*)(gWtHi + (size_t)nn * Kn * Fn);
            #pragma unroll
            for (int t = 0; t < 4; t++) {
                int id = tid + t * 256;
                int r = id >> 4, c = id & 15;
                CP_ASYNC16(pb + swz(r, c), srcH + r * 256 + c * 16);
            }
            CP_COMMIT();
        }

        float acc[2][8][4];
        #pragma unroll
        for (int mt = 0; mt < 2; mt++)
            #pragma unroll
            for (int nt = 0; nt < 8; nt++)
                #pragma unroll
                for (int e = 0; e < 4; e++) acc[mt][nt][e] = 0.f;

        #pragma unroll
        for (int ks = 0; ks < 8; ks++) {
            const int c0 = 2 * ks;
            uint32_t Ah[2][4], Bh[8][2];
            #pragma unroll
            for (int mt = 0; mt < 2; mt++) {
                int row = m0 + mt * 16 + (lane & 15);
                int cc  = c0 + (lane >> 4);
                ldm_x4(Ah[mt][0], Ah[mt][1], Ah[mt][2], Ah[mt][3], sb + SXH + swz(row, cc));
            }
            #pragma unroll
            for (int np = 0; np < 4; np++) {
                int nrow = np * 16 + (lane & 7) + ((lane >> 4) << 3);
                int cc   = c0 + ((lane >> 3) & 1);
                ldm_x4(Bh[np*2][0], Bh[np*2][1], Bh[np*2+1][0], Bh[np*2+1][1], wb + swz(nrow, cc));
            }
            #pragma unroll
            for (int mt = 0; mt < 2; mt++)
                #pragma unroll
                for (int nt = 0; nt < 8; nt++)
                    mma_bf16(acc[mt][nt], Ah[mt], Bh[nt]);
        }

        float pa = 0.f, pb2 = 0.f, pc = 0.f, pd = 0.f;
        #pragma unroll
        for (int nt = 0; nt < 8; nt++) {
            pa  += acc[0][nt][0] * acc[0][nt][0] + acc[0][nt][1] * acc[0][nt][1];
            pb2 += acc[0][nt][2] * acc[0][nt][2] + acc[0][nt][3] * acc[0][nt][3];
            pc  += acc[1][nt][0] * acc[1][nt][0] + acc[1][nt][1] * acc[1][nt][1];
            pd  += acc[1][nt][2] * acc[1][nt][2] + acc[1][nt][3] * acc[1][nt][3];
        }
        #pragma unroll
        for (int o = 1; o <= 2; o <<= 1) {
            pa  += __shfl_xor_sync(0xFFFFFFFFu, pa, o);
            pb2 += __shfl_xor_sync(0xFFFFFFFFu, pb2, o);
            pc  += __shfl_xor_sync(0xFFFFFFFFu, pc, o);
            pd  += __shfl_xor_sync(0xFFFFFFFFu, pd, o);
        }
        if ((lane & 3) == 0) {
            int r = lane >> 2;
            float* q = gQ + (size_t)n * Bn + bt * BT + m0;
            q[r]      = pa;
            q[r + 8]  = pb2;
            q[r + 16] = pc;
            q[r + 24] = pd;
        }

        CP_WAIT0();
        __syncthreads();
    }
}

// ============================================================================
// Kernel 3: argmax over n (4 lanes/sample, q's in registers); flag ambiguous;
// emit candidate pairs with ONE atomicAdd per lane; labels + loss.
// ============================================================================
__global__ void __launch_bounds__(256) reduce_kernel(const float* __restrict__ x,
                                                     float* __restrict__ out,
                                                     int out_size) {
    const int g = threadIdx.x & 3;
    const int b = (blockIdx.x * 256 + threadIdx.x) >> 2;
    const int lane = threadIdx.x & 31;

    float v[16];
    float q1 = -1e30f, q2 = -1e30f;
    int i1 = 0;
    #pragma unroll
    for (int t = 0; t < 16; t++) {
        int n = t * 4 + g;
        v[t] = gQ[n * Bn + b];
        if (v[t] > q1)      { q2 = q1; q1 = v[t]; i1 = n; }
        else if (v[t] > q2) { q2 = v[t]; }
    }
    #pragma unroll
    for (int o = 1; o <= 2; o <<= 1) {
        float oq1 = __shfl_xor_sync(0xFFFFFFFFu, q1, o);
        int   oi1 = __shfl_xor_sync(0xFFFFFFFFu, i1, o);
        float oq2 = __shfl_xor_sync(0xFFFFFFFFu, q2, o);
        if (oq1 > q1 || (oq1 == q1 && oi1 < i1)) {
            q2 = fmaxf(q1, fmaxf(q2, oq2));
            q1 = oq1; i1 = oi1;
        } else {
            q2 = fmaxf(oq1, fmaxf(q2, oq2));
        }
    }

    float xn2 = 0.f;
    const float4* xb = (const float4*)(x + (size_t)b * Fn);
    #pragma unroll
    for (int t = 0; t < 8; t++) {
        float4 f = xb[g + t * 4];
        xn2 += f.x * f.x + f.y * f.y + f.z * f.z + f.w * f.w;
    }
    #pragma unroll
    for (int o = 1; o <= 2; o <<= 1) xn2 += __shfl_xor_sync(0xFFFFFFFFu, xn2, o);

    const bool flagged = (q1 - q2 < q1 * THRV);

    if (g == 0) {
        if (out_size >= Bn + 1)  out[1 + b] = (float)i1;
        else if (out_size == Bn) out[b] = (float)i1;
        if (flagged) {
            int slot = atomicAdd(&gFlagCnt, 1);
            gFlagIdx[slot] = b;
            gFlagQ[slot] = q1;
            gBest[b] = 0ull;
        }
    }
    // lane-aggregated candidate emission (argmax pair included by construction)
    if (flagged) {
        const float cut = q1 * (1.0f - THRV);
        unsigned qual = 0;
        #pragma unroll
        for (int t = 0; t < 16; t++) if (v[t] >= cut) qual |= (1u << t);
        int cloc = __popc(qual);
        if (cloc) {
            int pos = atomicAdd(&gPairCnt, cloc);
            #pragma unroll
            for (int t = 0; t < 16; t++) {
                if (qual & (1u << t)) {
                    if (pos < MAXPAIR) gPair[pos] = (b << 6) | (t * 4 + g);
                    pos++;
                }
            }
        }
    }

    float resid = 0.25f * (xn2 - q1);
    #pragma unroll
    for (int o = 16; o; o >>= 1) resid += __shfl_xor_sync(0xFFFFFFFFu, resid, o);
    if (lane == 0 && out_size != Bn) atomicAdd(&out[0], resid);
}

// ============================================================================
// Kernel 4: cluster-major exact refine, W in smem (read ONCE per CTA).
// 256 CTAs: n = blk & 63, quarter = blk >> 6. Warps ballot-scan their slice
// of the pair list and process matching pairs from smem W — no per-pair L2 W reads.
// ============================================================================
__global__ void __launch_bounds__(256) refine_kernel(const float* __restrict__ x) {
    __shared__ float sW[Fn * Kn];      // 32 KB, [i][k]
    __shared__ float sx[8][Fn];        // per-warp x cache
    const int n = blockIdx.x & 63;
    const int quarter = blockIdx.x >> 6;
    const int wid = threadIdx.x >> 5, lane = threadIdx.x & 31;

    const float4* srcW = (const float4*)(gWf + (size_t)n * Fn * Kn);
    for (int i = threadIdx.x; i < Fn * Kn / 4; i += 256) ((float4*)sW)[i] = srcW[i];
    __syncthreads();

    const int cnt = min(gPairCnt, MAXPAIR);
    const int qlo = (cnt * quarter) >> 2, qhi = (cnt * (quarter + 1)) >> 2;

    for (int base = qlo + wid * 32; base < qhi; base += 8 * 32) {
        int idx = base + lane;
        int p = (idx < qhi) ? gPair[idx] : -1;
        bool match = (p >= 0) && ((p & 63) == n);
        unsigned mask = __ballot_sync(0xFFFFFFFFu, match);
        while (mask) {
            int srcl = __ffs(mask) - 1;
            mask &= mask - 1;
            int pp = __shfl_sync(0xFFFFFFFFu, p, srcl);
            int b = pp >> 6;

            ((float4*)sx[wid])[lane] = ((const float4*)(x + (size_t)b * Fn))[lane];
            __syncwarp();

            const float2* Wp = (const float2*)(sW + 2 * lane);  // lane owns k=2l,2l+1
            float z0 = 0.f, z1 = 0.f;
            #pragma unroll 8
            for (int i = 0; i < Fn; i++) {
                float xi = sx[wid][i];
                float2 wv = Wp[i * 32];
                z0 += xi * wv.x;
                z1 += xi * wv.y;
            }
            float qp = z0 * z0 + z1 * z1;
            #pragma unroll
            for (int o = 16; o; o >>= 1) qp += __shfl_xor_sync(0xFFFFFFFFu, qp, o);
            if (lane == 0) {
                unsigned long long pk = (((unsigned long long)__float_as_uint(qp)) << 32)
                                      | (unsigned)(Nn - 1 - n);   // smaller n wins ties
                atomicMax(&gBest[b], pk);
            }
            __syncwarp();
        }
    }
}

// ============================================================================
// Kernel 5: fixup — exact labels + loss corrections for flagged samples.
// ============================================================================
__global__ void __launch_bounds__(256) fixup_kernel(float* __restrict__ out, int out_size) {
    const int t = blockIdx.x * 256 + threadIdx.x;
    if (t >= gFlagCnt) return;
    const int b = gFlagIdx[t];
    const float qA = gFlagQ[t];
    unsigned long long pk = gBest[b];
    float qE = __uint_as_float((unsigned)(pk >> 32));
    int   nE = Nn - 1 - (int)(pk & 0xFFFFFFFFull);
    if (out_size >= Bn + 1)  out[1 + b] = (float)nE;
    else if (out_size == Bn) out[b] = (float)nE;
    if (out_size != Bn) atomicAdd(&out[0], qA - qE);
}

// ============================================================================
extern "C" void kernel_launch(void* const* d_in, const int* in_sizes, int n_in,
                              void* d_out, int out_size) {
    const float* x;
    const float* D;
    if (in_sizes[0] == Bn * Fn) { x = (const float*)d_in[0]; D = (const float*)d_in[1]; }
    else                        { x = (const float*)d_in[1]; D = (const float*)d_in[0]; }
    float* out = (float*)d_out;

    const int SMEM_PREP = (Fn * Kn + 64 * 65 + 64 + Fn * 65) * 4;
    cudaFuncSetAttribute(prep_kernel, cudaFuncAttributeMaxDynamicSharedMemorySize, SMEM_PREP);
    cudaFuncSetAttribute(main_kernel, cudaFuncAttributeMaxDynamicSharedMemorySize, SM_TOTAL);

    convert_x_kernel<<<Bn * Fn / (256 * 8), 256>>>(x);
    prep_kernel<<<Nn, 256, SMEM_PREP>>>(D);
    dummy_kernel<<<1, 32>>>();
    main_kernel<<<dim3(Bn / BT, Nn / NG), 256, SM_TOTAL>>>();
    if (out_size != Bn) cudaMemsetAsync(d_out, 0, sizeof(float));
    reduce_kernel<<<Bn * 4 / 256, 256>>>(x, out, out_size);
    refine_kernel<<<256, 256>>>(x);
    fixup_kernel<<<Bn / 256, 256>>>(out, out_size);
}